// round 11
// baseline (speedup 1.0000x reference)
#include <cuda_runtime.h>
#include <cuda_bf16.h>
#include <cuda_fp16.h>

#define NB 4
#define NC 15
#define HH 320
#define FEATS 32
#define KS 11
#define KRBF 31
#define PH 342      // reflect-padded size (320 + 2*11)
#define UPD 352     // reflect + zero conv pad (342 + 2*5)
#define FUP 344     // pitch for f_u_k rows

// ---------------- static device scratch (no allocations allowed) ----------
__device__ float2 g_up[NB*UPD*UPD];          // (ur,ui) padded input
__device__ float  g_fu[NB*FEATS*PH*FUP];     // RBF(conv(u))
__device__ float2 g_ru[NB*HH*HH];            // regularizer output (cropped, /32)
__device__ float2 g_ks[NB*NC*HH*HH];         // k-space scratch

// ---------------- complex helpers ----------------
__device__ __forceinline__ float2 cmul(float2 a, float2 b){
    return make_float2(fmaf(a.x, b.x, -a.y*b.y), fmaf(a.x, b.y, a.y*b.x));
}
__device__ __forceinline__ float2 cadd(float2 a, float2 b){
    return make_float2(a.x+b.x, a.y+b.y);
}
__device__ __forceinline__ float2 cexp_(float ang){
    float s, c; __sincosf(ang, &s, &c); return make_float2(c, s);
}

#define TWO_PI 6.28318530717958647692f

// ---------------- fp16 mma helpers -----------------------------------------
__device__ __forceinline__ unsigned pack_h2(float a, float b){
    __half2 h = __floats2half2_rn(a, b);
    return *reinterpret_cast<unsigned*>(&h);
}
__device__ __forceinline__ void mma_f16(float* d, const unsigned* a, const unsigned* b){
    asm volatile("mma.sync.aligned.m16n8k16.row.col.f32.f16.f16.f32 "
        "{%0,%1,%2,%3}, {%4,%5,%6,%7}, {%8,%9}, {%0,%1,%2,%3};"
        : "+f"(d[0]), "+f"(d[1]), "+f"(d[2]), "+f"(d[3])
        : "r"(a[0]), "r"(a[1]), "r"(a[2]), "r"(a[3]), "r"(b[0]), "r"(b[1]));
}

// ---------------- 320-point Stockham FFT (radix 5*4*4*4) ------------------
__device__ __forceinline__ void r4stage(const float2* __restrict__ src,
                                        float2* __restrict__ dst,
                                        int lt, int S, int M, int NN, float ds){
    int q = lt % S;
    int p = lt / S;            // p < M
    float2 a0 = src[q + S*p];
    float2 a1 = src[q + S*(p +   M)];
    float2 a2 = src[q + S*(p + 2*M)];
    float2 a3 = src[q + S*(p + 3*M)];
    float2 t0 = make_float2(a0.x+a2.x, a0.y+a2.y);
    float2 t1 = make_float2(a0.x-a2.x, a0.y-a2.y);
    float2 t2 = make_float2(a1.x+a3.x, a1.y+a3.y);
    float2 t3 = make_float2(a1.x-a3.x, a1.y-a3.y);
    float2 it3 = make_float2(-ds*t3.y, ds*t3.x);   // ds*i*t3
    float2 c0 = make_float2(t0.x+t2.x, t0.y+t2.y);
    float2 c2 = make_float2(t0.x-t2.x, t0.y-t2.y);
    float2 c1 = make_float2(t1.x+it3.x, t1.y+it3.y);
    float2 c3 = make_float2(t1.x-it3.x, t1.y-it3.y);
    float base = ds * TWO_PI * (float)p / (float)NN;
    dst[q + S*(4*p + 0)] = c0;
    dst[q + S*(4*p + 1)] = cmul(c1, cexp_(base));
    dst[q + S*(4*p + 2)] = cmul(c2, cexp_(base*2.f));
    dst[q + S*(4*p + 3)] = cmul(c3, cexp_(base*3.f));
}

__device__ void fft320(float2* __restrict__ A, float2* __restrict__ B,
                       int lt, float ds){
    if (lt < 64){
        int p = lt;
        float2 a0 = A[p], a1 = A[p+64], a2 = A[p+128], a3 = A[p+192], a4 = A[p+256];
        B[5*p] = cadd(cadd(cadd(a0,a1), cadd(a2,a3)), a4);
        #pragma unroll
        for (int k = 1; k < 5; k++){
            float2 w1 = cexp_(ds * TWO_PI * 0.2f * (float)k);
            float2 wj = w1;
            float2 c = a0;
            c = cadd(c, cmul(a1, wj)); wj = cmul(wj, w1);
            c = cadd(c, cmul(a2, wj)); wj = cmul(wj, w1);
            c = cadd(c, cmul(a3, wj)); wj = cmul(wj, w1);
            c = cadd(c, cmul(a4, wj));
            float2 tw = cexp_(ds * TWO_PI * (float)(p*k) / 320.0f);
            B[5*p + k] = cmul(c, tw);
        }
    }
    __syncthreads();
    r4stage(B, A, lt,  5, 16, 64, ds);
    __syncthreads();
    r4stage(A, B, lt, 20,  4, 16, ds);
    __syncthreads();
    r4stage(B, A, lt, 80,  1,  4, ds);
    __syncthreads();
}

// ---------------- K1: reflect + zero padding -------------------------------
__global__ void kpad(const float* __restrict__ u){
    int idx = blockIdx.x * blockDim.x + threadIdx.x;
    if (idx >= NB*UPD*UPD) return;
    int n  = idx / (UPD*UPD);
    int r  = idx % (UPD*UPD);
    int py = r / UPD, px = r % UPD;
    float2 v = make_float2(0.f, 0.f);
    if (!(py < 5 || py >= 347 || px < 5 || px >= 347)){
        int iy = py - 16, ix = px - 16;
        if (iy < 0) iy = -iy; else if (iy >= HH) iy = 2*HH - 2 - iy;
        if (ix < 0) ix = -ix; else if (ix >= HH) ix = 2*HH - 2 - ix;
        v = ((const float2*)u)[(n*HH + iy)*HH + ix];
    }
    g_up[idx] = v;
}

// ---------------- K2: fwd conv (2->32 ch) via fp16 MMA + fast RBF ----------
// block = 256 thr (8 warps); spatial tile 32 wide x 16 tall = 512 pixels.
// K: 121 taps (re,im packed as half2 k-pairs) padded to 128 -> 16 mma steps.
__global__ __launch_bounds__(256, 2) void kconv_mma(const float* __restrict__ ck,
                                                    const float* __restrict__ w_,
                                                    const float* __restrict__ mu_,
                                                    const float* __restrict__ sigma_){
    __shared__ unsigned s_in[26*42];      // half2 (re,im) input tile
    __shared__ unsigned s_B[128*40];      // half2 (wr,wi) [tap][oc], pitch 40 (conflict-free)
    __shared__ int   s_off[128];          // per-tap offset into s_in (half2 units)
    __shared__ float s_wx[FEATS*40];      // RBF weights, zero-padded by 4 each side
    __shared__ float s_mu[KRBF];

    int nb = blockIdx.z;
    int x0 = blockIdx.x * 32, y0 = blockIdx.y * 16;
    int tid = threadIdx.x;

    // fills
    for (int i = tid; i < 128; i += 256){
        int ky = i / 11, kx = i - ky*11;
        s_off[i] = (i < 121) ? (ky*42 + kx) : 0;
    }
    for (int i = tid; i < 128*32; i += 256){
        int tap = i >> 5, oc = i & 31;
        unsigned v = 0u;
        if (tap < 121)
            v = pack_h2(ck[oc*242 + tap*2], ck[oc*242 + tap*2 + 1]);
        s_B[tap*40 + oc] = v;
    }
    for (int i = tid; i < FEATS*40; i += 256){
        int oc = i / 40, kk = i - oc*40;
        s_wx[i] = (kk >= 4 && kk < 4 + KRBF) ? w_[oc*KRBF + kk - 4] : 0.f;
    }
    if (tid < KRBF) s_mu[tid] = mu_[tid];
    const float2* up = g_up + nb*UPD*UPD;
    for (int i = tid; i < 26*42; i += 256){
        int r = i / 42, c = i - r*42;
        int y = y0 + r, x = x0 + c;
        float2 v = (y < UPD && x < UPD) ? up[y*UPD + x] : make_float2(0.f, 0.f);
        s_in[i] = pack_h2(v.x, v.y);
    }
    __syncthreads();

    int lane = tid & 31, warp = tid >> 5;
    int grp  = lane >> 2, four = lane & 3;

    int pb[4][2];
    #pragma unroll
    for (int m = 0; m < 4; m++){
        int p0 = warp*64 + m*16 + grp;
        pb[m][0] = (p0 >> 5)*42 + (p0 & 31);
        int p1 = p0 + 8;
        pb[m][1] = (p1 >> 5)*42 + (p1 & 31);
    }

    float acc[4][4][4];
    #pragma unroll
    for (int m = 0; m < 4; m++)
        #pragma unroll
        for (int n = 0; n < 4; n++)
            #pragma unroll
            for (int r = 0; r < 4; r++) acc[m][n][r] = 0.f;

    #pragma unroll 1
    for (int s = 0; s < 16; s++){
        int t0 = s*8 + four, t1 = t0 + 4;
        int o0 = s_off[t0], o1 = s_off[t1];
        unsigned a[4][4];
        #pragma unroll
        for (int m = 0; m < 4; m++){
            a[m][0] = s_in[pb[m][0] + o0];
            a[m][1] = s_in[pb[m][1] + o0];
            a[m][2] = s_in[pb[m][0] + o1];
            a[m][3] = s_in[pb[m][1] + o1];
        }
        unsigned b[4][2];
        #pragma unroll
        for (int n = 0; n < 4; n++){
            b[n][0] = s_B[t0*40 + n*8 + grp];
            b[n][1] = s_B[t1*40 + n*8 + grp];
        }
        #pragma unroll
        for (int m = 0; m < 4; m++)
            #pragma unroll
            for (int n = 0; n < 4; n++)
                mma_f16(acc[m][n], a[m], b[n]);
    }

    // ---- epilogue: factored RBF + store ----
    float sg    = sigma_[0];
    float h     = 0.5f / (sg * sg);
    float mu0   = s_mu[0];
    float delta = s_mu[1] - s_mu[0];
    float idel  = 1.f / delta;
    float c2    = 2.f * h * delta;
    float C1    = __expf(-h * delta * delta);
    float C1_2  = C1*C1;
    float C4    = C1_2*C1_2;
    float C8    = C4*C4;
    float C16   = C8*C8;
    float C9    = C8*C1;
    float tmax  = 10.f / (h * delta);

    #pragma unroll
    for (int m = 0; m < 4; m++){
        #pragma unroll
        for (int n = 0; n < 4; n++){
            #pragma unroll
            for (int r2 = 0; r2 < 4; r2++){
                int row = grp + ((r2 >> 1) << 3);
                int col = (four << 1) + (r2 & 1);
                int p  = warp*64 + m*16 + row;
                int gy = y0 + (p >> 5), gx = x0 + (p & 31);
                if (gy < PH && gx < PH){
                    int oc = n*8 + col;
                    float v = acc[m][n][r2];
                    int j = __float2int_rn((v - mu0) * idel);
                    j = max(0, min(KRBF-1, j));
                    float t = v - fmaf((float)j, delta, mu0);
                    t = fminf(fmaxf(t, -tmax), tmax);
                    float E0 = __expf(-h*t*t);
                    float gpl = __expf(c2*t);
                    float gmi = __expf(-c2*t);
                    float g2 = gpl*gpl, g3 = g2*gpl, g4 = g2*g2;
                    float q2 = gmi*gmi, q3 = q2*gmi, q4 = q2*q2;
                    const float* wp = s_wx + oc*40 + j;
                    float s_ = wp[4]
                        + C1 *(wp[5]*gpl + wp[3]*gmi)
                        + C4 *(wp[6]*g2  + wp[2]*q2)
                        + C9 *(wp[7]*g3  + wp[1]*q3)
                        + C16*(wp[8]*g4  + wp[0]*q4);
                    g_fu[((nb*FEATS + oc)*PH + gy)*FUP + gx] = E0 * s_;
                }
            }
        }
    }
}

// ---------------- K3: transposed conv via fp16 MMA (shifted-PS trick) ------
// out[Y,X] = sum_j PS_j[Y,X+j];  PS_j GEMM: K packed as half2 pairs over kx-quads.
// k2 = ky*2+h (22 real, pad to 24): h=0 -> elements (q=0,q=1), h=1 -> (q=2, 0).
#define CTW 29
__global__ __launch_bounds__(256) void kconvT_mma(const float* __restrict__ ck){
    __shared__ unsigned s_B[FEATS*24*8];   // [oc][k2][n] half2 weights (24.6KB)
    __shared__ unsigned s_P[26*68];        // packed G: [r][0..36)=(c,c+4)  [r][36..68)=(c+8,0)
    __shared__ int   s_koff[24];

    int nb = blockIdx.z;
    int x0 = blockIdx.x * CTW, y0 = blockIdx.y * 16;
    int tid = threadIdx.x;
    int lane = tid & 31, warp = tid >> 5;
    int grp  = lane >> 2, four = lane & 3;

    // B fill: k2=(ky,h), n=(comp*4+j); flipped kernel; kx = q*4+j
    for (int i = tid; i < FEATS*24*8; i += 256){
        int oc = i / (24*8);
        int r  = i - oc*(24*8);
        int k2 = r >> 3, n = r & 7;
        int comp = n >> 2, j = n & 3;
        int ky = k2 >> 1, h = k2 & 1;
        float v0 = 0.f, v1 = 0.f;
        if (k2 < 22){
            int kx0 = h ? (8 + j) : j;
            if (kx0 <= 10) v0 = ck[(oc*121 + (10-ky)*11 + (10-kx0))*2 + comp];
            if (!h){
                int kx1 = 4 + j;
                v1 = ck[(oc*121 + (10-ky)*11 + (10-kx1))*2 + comp];
            }
        }
        s_B[i] = pack_h2(v0, v1);
    }
    for (int i = tid; i < 24; i += 256){
        int ky = i >> 1, h = i & 1;
        s_koff[i] = (i < 22) ? (ky*68 + h*36) : 0;
    }

    int pb[4][2];
    #pragma unroll
    for (int m = 0; m < 4; m++){
        int p0 = warp*64 + m*16 + grp;
        pb[m][0] = (p0 >> 5)*68 + (p0 & 31);
        int p1 = p0 + 8;
        pb[m][1] = (p1 >> 5)*68 + (p1 & 31);
    }

    float acc[4][4];
    #pragma unroll
    for (int m = 0; m < 4; m++)
        #pragma unroll
        for (int r = 0; r < 4; r++) acc[m][r] = 0.f;

    #pragma unroll 1
    for (int oc = 0; oc < FEATS; oc++){
        __syncthreads();
        const float* fup = g_fu + (nb*FEATS + oc)*PH*FUP;
        for (int i = tid; i < 26*68; i += 256){
            int r = i / 68, c = i - r*68;
            int gr = (y0 + 6 + r)*FUP + x0 + 6;
            float v0, v1;
            if (c < 36){
                int gc0 = x0 + 6 + c;
                v0 = (gc0     < FUP) ? fup[gr + c]     : 0.f;
                v1 = (gc0 + 4 < FUP) ? fup[gr + c + 4] : 0.f;
            } else {
                int cc = c - 36;
                int gc0 = x0 + 6 + cc + 8;
                v0 = (gc0 < FUP) ? fup[gr + cc + 8] : 0.f;
                v1 = 0.f;
            }
            s_P[i] = pack_h2(v0, v1);
        }
        __syncthreads();

        const unsigned* Boc = s_B + oc*24*8;
        #pragma unroll
        for (int s = 0; s < 3; s++){
            int k2a = s*8 + four, k2b = k2a + 4;
            int o0 = s_koff[k2a], o1 = s_koff[k2b];
            unsigned b[2];
            b[0] = Boc[k2a*8 + grp];
            b[1] = Boc[k2b*8 + grp];
            #pragma unroll
            for (int m = 0; m < 4; m++){
                unsigned a[4];
                a[0] = s_P[pb[m][0] + o0];
                a[1] = s_P[pb[m][1] + o0];
                a[2] = s_P[pb[m][0] + o1];
                a[3] = s_P[pb[m][1] + o1];
                mma_f16(acc[m], a, b);
            }
        }
    }

    // combine shifted partial sums through smem (alias s_B; mma phase done)
    __syncthreads();
    float* s_PS = (float*)s_B;       // needs 512*9 = 4608 floats <= 6144
    #pragma unroll
    for (int m = 0; m < 4; m++){
        #pragma unroll
        for (int r2 = 0; r2 < 4; r2++){
            int p = warp*64 + m*16 + grp + ((r2 >> 1) << 3);
            int n = (four << 1) + (r2 & 1);
            s_PS[p*9 + n] = acc[m][r2];
        }
    }
    __syncthreads();

    const float inv = 1.f / (float)FEATS;
    for (int i = tid; i < 512; i += 256){
        int row = i >> 5, col = i & 31;
        int X = x0 + col, Y = y0 + row;
        if (col < CTW && X < HH){
            float orr = 0.f, oii = 0.f;
            #pragma unroll
            for (int j = 0; j < 4; j++){
                orr += s_PS[(i + j)*9 + j];
                oii += s_PS[(i + j)*9 + 4 + j];
            }
            g_ru[(nb*HH + Y)*HH + X] = make_float2(orr*inv, oii*inv);
        }
    }
}

// ---------------- D1: row forward FFT of s*(u*coil) ------------------------
__global__ __launch_bounds__(320) void kfft_row_fwd(const float* __restrict__ u,
                                                    const float* __restrict__ coil){
    __shared__ float2 SA[4][320], SB[4][320];
    int b    = blockIdx.x;
    int ygrp = b % 80;
    int nc   = b / 80;
    int c    = nc % NC, n = nc / NC;
    int t    = threadIdx.x;
    int line = t / 80, lt = t % 80;
    int y    = ygrp*4 + line;

    const float2* up = (const float2*)u    + (n*HH + y)*HH;
    const float2* cp = (const float2*)coil + ((n*NC + c)*HH + y)*HH;
    #pragma unroll
    for (int j = 0; j < 4; j++){
        int x = lt + 80*j;
        float2 v = cmul(up[x], cp[x]);
        float sg = ((x + y) & 1) ? -1.f : 1.f;
        SA[line][x] = make_float2(v.x*sg, v.y*sg);
    }
    __syncthreads();
    fft320(SA[line], SB[line], lt, -1.f);

    float2* dst = g_ks + ((n*NC + c)*HH + y)*HH;
    #pragma unroll
    for (int j = 0; j < 4; j++){ int x = lt + 80*j; dst[x] = SA[line][x]; }
}

// ---------------- D2: column fwd FFT + mask/subtract + column inv FFT ------
__global__ __launch_bounds__(320) void kfft_col(const float* __restrict__ f,
                                                const float* __restrict__ mask){
    __shared__ float2 SA[4][320], SB[4][320];
    int b    = blockIdx.x;
    int xgrp = b % 80;
    int nc   = b / 80;
    int c    = nc % NC, n = nc / NC;
    int t    = threadIdx.x;
    int line = t & 3, lt = t >> 2;
    int x    = xgrp*4 + line;

    float2* col = g_ks + (n*NC + c)*HH*HH + x;
    #pragma unroll
    for (int j = 0; j < 4; j++){ int y = lt + 80*j; SA[line][y] = col[y*HH]; }
    __syncthreads();
    fft320(SA[line], SB[line], lt, -1.f);

    const float sc = 1.f / 320.f;
    #pragma unroll
    for (int j = 0; j < 4; j++){
        int ky = lt + 80*j;
        float2 V = SA[line][ky];
        float  m = mask[(n*HH + ky)*HH + x];
        float2 fv = ((const float2*)f)[((n*NC + c)*HH + ky)*HH + x];
        float sg = ((ky + x) & 1) ? -1.f : 1.f;
        float wx = m * (V.x*sc - sg*fv.x);
        float wy = m * (V.y*sc - sg*fv.y);
        SA[line][ky] = make_float2(wx*sc, wy*sc);
    }
    __syncthreads();
    fft320(SA[line], SB[line], lt, 1.f);
    #pragma unroll
    for (int j = 0; j < 4; j++){ int y = lt + 80*j; col[y*HH] = SA[line][y]; }
}

// ---------------- D3: row inverse FFT + coil-combine + final output --------
__global__ __launch_bounds__(320) void kfft_row_inv(const float* __restrict__ u,
                                                    const float* __restrict__ coil,
                                                    const float* __restrict__ lamb,
                                                    float* __restrict__ outp){
    __shared__ float2 SA[4][320], SB[4][320];
    int b    = blockIdx.x;
    int ygrp = b % 80;
    int n    = b / 80;
    int t    = threadIdx.x;
    int line = t / 80, lt = t % 80;
    int y    = ygrp*4 + line;

    float2 du[4];
    #pragma unroll
    for (int j = 0; j < 4; j++) du[j] = make_float2(0.f, 0.f);

    for (int c = 0; c < NC; c++){
        const float2* src = g_ks + ((n*NC + c)*HH + y)*HH;
        __syncthreads();
        #pragma unroll
        for (int j = 0; j < 4; j++){ int x = lt + 80*j; SA[line][x] = src[x]; }
        __syncthreads();
        fft320(SA[line], SB[line], lt, 1.f);

        const float2* cp = (const float2*)coil + ((n*NC + c)*HH + y)*HH;
        #pragma unroll
        for (int j = 0; j < 4; j++){
            int x = lt + 80*j;
            float2 w2 = SA[line][x];
            float2 cc = cp[x];
            float sg = ((x + y) & 1) ? -1.f : 1.f;
            du[j].x += sg * ( w2.x*cc.x + w2.y*cc.y);
            du[j].y += sg * ( w2.y*cc.x - w2.x*cc.y);
        }
    }

    float lam = lamb[0];
    const float2* up  = (const float2*)u + (n*HH + y)*HH;
    const float2* rup = g_ru + (n*HH + y)*HH;
    float2* op = (float2*)outp + (n*HH + y)*HH;
    #pragma unroll
    for (int j = 0; j < 4; j++){
        int x = lt + 80*j;
        float2 uv = up[x];
        float2 rv = rup[x];
        op[x] = make_float2(uv.x - rv.x - lam*du[j].x,
                            uv.y - rv.y - lam*du[j].y);
    }
}

// ---------------- launch ---------------------------------------------------
extern "C" void kernel_launch(void* const* d_in, const int* in_sizes, int n_in,
                              void* d_out, int out_size){
    const float* u     = (const float*)d_in[0];   // (4,320,320,2)
    const float* f     = (const float*)d_in[1];   // (4,15,320,320,2)
    const float* coil  = (const float*)d_in[2];   // (4,15,320,320,2)
    const float* mask  = (const float*)d_in[3];   // (4,320,320)
    const float* ck    = (const float*)d_in[4];   // (32,1,11,11,2)
    const float* w_    = (const float*)d_in[5];   // (1,32,1,1,31)
    const float* mu_   = (const float*)d_in[6];   // (31,)
    const float* sig   = (const float*)d_in[7];   // (1,)
    const float* lamb  = (const float*)d_in[8];   // (1,)
    float* outp = (float*)d_out;

    kpad<<<(NB*UPD*UPD + 255)/256, 256>>>(u);
    kconv_mma<<<dim3(11, 22, NB), 256>>>(ck, w_, mu_, sig);
    kconvT_mma<<<dim3(12, 20, NB), 256>>>(ck);
    kfft_row_fwd<<<NB*NC*80, 320>>>(u, coil);
    kfft_col<<<NB*NC*80, 320>>>(f, mask);
    kfft_row_inv<<<NB*80, 320>>>(u, coil, lamb, outp);
}

// round 13
// speedup vs baseline: 1.0564x; 1.0564x over previous
#include <cuda_runtime.h>
#include <cuda_bf16.h>

#define NB 4
#define NC 15
#define HH 320
#define FEATS 32
#define KS 11
#define KRBF 31
#define PH 342      // reflect-padded size (320 + 2*11)
#define UPD 352     // reflect + zero conv pad (342 + 2*5)
#define FUP 344     // pitch for f_u_k rows

// ---------------- static device scratch (no allocations allowed) ----------
__device__ float2 g_up[NB*UPD*UPD];          // (ur,ui) padded input
__device__ float  g_fu[NB*FEATS*PH*FUP];     // RBF(conv(u))
__device__ float2 g_ru[NB*HH*HH];            // regularizer output (cropped, /32)
__device__ float2 g_ks[NB*NC*HH*HH];         // k-space scratch
__device__ float  g_Bt[FEATS*40*8];          // convT tf32 weights [oc][k(40)][n(8)]

// ---------------- complex helpers ----------------
__device__ __forceinline__ float2 cmul(float2 a, float2 b){
    return make_float2(fmaf(a.x, b.x, -a.y*b.y), fmaf(a.x, b.y, a.y*b.x));
}
__device__ __forceinline__ float2 cadd(float2 a, float2 b){
    return make_float2(a.x+b.x, a.y+b.y);
}
__device__ __forceinline__ float2 cexp_(float ang){
    float s, c; __sincosf(ang, &s, &c); return make_float2(c, s);
}

#define TWO_PI 6.28318530717958647692f

// ---------------- tf32 helpers --------------------------------------------
__device__ __forceinline__ float to_tf32(float x){
    float r; asm("cvt.rna.tf32.f32 %0, %1;" : "=f"(r) : "f"(x)); return r;
}
__device__ __forceinline__ void mma_tf32(float* d, const unsigned* a, const unsigned* b){
    asm volatile("mma.sync.aligned.m16n8k8.row.col.f32.tf32.tf32.f32 "
        "{%0,%1,%2,%3}, {%4,%5,%6,%7}, {%8,%9}, {%0,%1,%2,%3};"
        : "+f"(d[0]), "+f"(d[1]), "+f"(d[2]), "+f"(d[3])
        : "r"(a[0]), "r"(a[1]), "r"(a[2]), "r"(a[3]), "r"(b[0]), "r"(b[1]));
}

// ---------------- 320-point Stockham FFT (radix 5*4*4*4) ------------------
__device__ __forceinline__ void r4stage(const float2* __restrict__ src,
                                        float2* __restrict__ dst,
                                        int lt, int S, int M, int NN, float ds){
    int q = lt % S;
    int p = lt / S;            // p < M
    float2 a0 = src[q + S*p];
    float2 a1 = src[q + S*(p +   M)];
    float2 a2 = src[q + S*(p + 2*M)];
    float2 a3 = src[q + S*(p + 3*M)];
    float2 t0 = make_float2(a0.x+a2.x, a0.y+a2.y);
    float2 t1 = make_float2(a0.x-a2.x, a0.y-a2.y);
    float2 t2 = make_float2(a1.x+a3.x, a1.y+a3.y);
    float2 t3 = make_float2(a1.x-a3.x, a1.y-a3.y);
    float2 it3 = make_float2(-ds*t3.y, ds*t3.x);   // ds*i*t3
    float2 c0 = make_float2(t0.x+t2.x, t0.y+t2.y);
    float2 c2 = make_float2(t0.x-t2.x, t0.y-t2.y);
    float2 c1 = make_float2(t1.x+it3.x, t1.y+it3.y);
    float2 c3 = make_float2(t1.x-it3.x, t1.y-it3.y);
    float base = ds * TWO_PI * (float)p / (float)NN;
    dst[q + S*(4*p + 0)] = c0;
    dst[q + S*(4*p + 1)] = cmul(c1, cexp_(base));
    dst[q + S*(4*p + 2)] = cmul(c2, cexp_(base*2.f));
    dst[q + S*(4*p + 3)] = cmul(c3, cexp_(base*3.f));
}

__device__ void fft320(float2* __restrict__ A, float2* __restrict__ B,
                       int lt, float ds){
    if (lt < 64){
        int p = lt;
        float2 a0 = A[p], a1 = A[p+64], a2 = A[p+128], a3 = A[p+192], a4 = A[p+256];
        B[5*p] = cadd(cadd(cadd(a0,a1), cadd(a2,a3)), a4);
        #pragma unroll
        for (int k = 1; k < 5; k++){
            float2 w1 = cexp_(ds * TWO_PI * 0.2f * (float)k);
            float2 wj = w1;
            float2 c = a0;
            c = cadd(c, cmul(a1, wj)); wj = cmul(wj, w1);
            c = cadd(c, cmul(a2, wj)); wj = cmul(wj, w1);
            c = cadd(c, cmul(a3, wj)); wj = cmul(wj, w1);
            c = cadd(c, cmul(a4, wj));
            float2 tw = cexp_(ds * TWO_PI * (float)(p*k) / 320.0f);
            B[5*p + k] = cmul(c, tw);
        }
    }
    __syncthreads();
    r4stage(B, A, lt,  5, 16, 64, ds);
    __syncthreads();
    r4stage(A, B, lt, 20,  4, 16, ds);
    __syncthreads();
    r4stage(B, A, lt, 80,  1,  4, ds);
    __syncthreads();
}

// ---------------- K0: precompute convT tf32 B matrix -----------------------
// k = ky*3+q (33 real, pad 40), n = comp*4+j; kx = 4q+j; flipped kernel.
__global__ void kprep(const float* __restrict__ ck){
    int i = blockIdx.x * 256 + threadIdx.x;
    if (i >= FEATS*40*8) return;
    int oc = i / 320;
    int r  = i - oc*320;
    int k  = r >> 3, n = r & 7;
    int ky = k / 3, q = k - ky*3;
    int comp = n >> 2, j = n & 3;
    int kx = 4*q + j;
    float v = 0.f;
    if (k < 33 && kx <= 10)
        v = to_tf32(ck[(oc*121 + (10-ky)*11 + (10-kx))*2 + comp]);
    g_Bt[i] = v;
}

// ---------------- K1: reflect + zero padding -------------------------------
__global__ void kpad(const float* __restrict__ u){
    int idx = blockIdx.x * blockDim.x + threadIdx.x;
    if (idx >= NB*UPD*UPD) return;
    int n  = idx / (UPD*UPD);
    int r  = idx % (UPD*UPD);
    int py = r / UPD, px = r % UPD;
    float2 v = make_float2(0.f, 0.f);
    if (!(py < 5 || py >= 347 || px < 5 || px >= 347)){
        int iy = py - 16, ix = px - 16;
        if (iy < 0) iy = -iy; else if (iy >= HH) iy = 2*HH - 2 - iy;
        if (ix < 0) ix = -ix; else if (ix >= HH) ix = 2*HH - 2 - ix;
        v = ((const float2*)u)[(n*HH + iy)*HH + ix];
    }
    g_up[idx] = v;
}

// ---------------- K2: fwd conv (2->32 ch) via tf32 MMA + fast RBF ----------
// (round-10 proven version)
__global__ __launch_bounds__(256, 2) void kconv_mma(const float* __restrict__ ck,
                                                    const float* __restrict__ w_,
                                                    const float* __restrict__ mu_,
                                                    const float* __restrict__ sigma_){
    __shared__ float s_in[26*42*2];       // tf32-rounded input tile (float2 interleaved)
    __shared__ float s_B[248*34];         // tf32 weights [k][oc], pitch 34
    __shared__ int   s_off[248];          // im2col offsets (floats) per k
    __shared__ float s_wx[FEATS*40];      // RBF weights, zero-padded by 4 each side
    __shared__ float s_mu[KRBF];

    int nb = blockIdx.z;
    int x0 = blockIdx.x * 32, y0 = blockIdx.y * 16;
    int tid = threadIdx.x;

    for (int i = tid; i < 248; i += 256){
        int tap = i >> 1, comp = i & 1;
        int ky = tap / 11, kx = tap - ky*11;
        s_off[i] = (i < 242) ? ((ky*42 + kx)*2 + comp) : 0;
    }
    for (int i = tid; i < 248*32; i += 256){
        int k = i >> 5, oc = i & 31;
        s_B[k*34 + oc] = (k < 242) ? to_tf32(ck[oc*242 + k]) : 0.f;
    }
    for (int i = tid; i < FEATS*40; i += 256){
        int oc = i / 40, kk = i - oc*40;
        s_wx[i] = (kk >= 4 && kk < 4 + KRBF) ? w_[oc*KRBF + kk - 4] : 0.f;
    }
    if (tid < KRBF) s_mu[tid] = mu_[tid];
    const float2* up = g_up + nb*UPD*UPD;
    for (int i = tid; i < 26*42; i += 256){
        int r = i / 42, c = i - r*42;
        int y = y0 + r, x = x0 + c;
        float2 v = (y < UPD && x < UPD) ? up[y*UPD + x] : make_float2(0.f, 0.f);
        s_in[2*i]   = to_tf32(v.x);
        s_in[2*i+1] = to_tf32(v.y);
    }
    __syncthreads();

    int lane = tid & 31, warp = tid >> 5;
    int grp  = lane >> 2, four = lane & 3;

    int pb[4][2];
    #pragma unroll
    for (int m = 0; m < 4; m++){
        int p0 = warp*64 + m*16 + grp;
        pb[m][0] = ((p0 >> 5)*42 + (p0 & 31))*2;
        int p1 = p0 + 8;
        pb[m][1] = ((p1 >> 5)*42 + (p1 & 31))*2;
    }

    float acc[4][4][4];
    #pragma unroll
    for (int m = 0; m < 4; m++)
        #pragma unroll
        for (int n = 0; n < 4; n++)
            #pragma unroll
            for (int r = 0; r < 4; r++) acc[m][n][r] = 0.f;

    #pragma unroll 1
    for (int kc = 0; kc < 31; kc++){
        int kk = kc*8 + four;
        int o0 = s_off[kk], o1 = s_off[kk + 4];
        unsigned a[4][4];
        #pragma unroll
        for (int m = 0; m < 4; m++){
            a[m][0] = __float_as_uint(s_in[pb[m][0] + o0]);
            a[m][1] = __float_as_uint(s_in[pb[m][1] + o0]);
            a[m][2] = __float_as_uint(s_in[pb[m][0] + o1]);
            a[m][3] = __float_as_uint(s_in[pb[m][1] + o1]);
        }
        unsigned b[4][2];
        #pragma unroll
        for (int n = 0; n < 4; n++){
            b[n][0] = __float_as_uint(s_B[kk*34       + n*8 + grp]);
            b[n][1] = __float_as_uint(s_B[(kk+4)*34   + n*8 + grp]);
        }
        #pragma unroll
        for (int m = 0; m < 4; m++)
            #pragma unroll
            for (int n = 0; n < 4; n++)
                mma_tf32(acc[m][n], a[m], b[n]);
    }

    // ---- epilogue: factored RBF + store ----
    float sg    = sigma_[0];
    float h     = 0.5f / (sg * sg);
    float mu0   = s_mu[0];
    float delta = s_mu[1] - s_mu[0];
    float idel  = 1.f / delta;
    float c2    = 2.f * h * delta;
    float C1    = __expf(-h * delta * delta);
    float C1_2  = C1*C1;
    float C4    = C1_2*C1_2;
    float C8    = C4*C4;
    float C16   = C8*C8;
    float C9    = C8*C1;
    float tmax  = 10.f / (h * delta);

    #pragma unroll
    for (int m = 0; m < 4; m++){
        #pragma unroll
        for (int n = 0; n < 4; n++){
            #pragma unroll
            for (int r2 = 0; r2 < 4; r2++){
                int row = grp + ((r2 >> 1) << 3);
                int col = (four << 1) + (r2 & 1);
                int p  = warp*64 + m*16 + row;
                int gy = y0 + (p >> 5), gx = x0 + (p & 31);
                if (gy < PH && gx < PH){
                    int oc = n*8 + col;
                    float v = acc[m][n][r2];
                    int j = __float2int_rn((v - mu0) * idel);
                    j = max(0, min(KRBF-1, j));
                    float t = v - fmaf((float)j, delta, mu0);
                    t = fminf(fmaxf(t, -tmax), tmax);
                    float E0 = __expf(-h*t*t);
                    float gpl = __expf(c2*t);
                    float gmi = __expf(-c2*t);
                    float g2 = gpl*gpl, g3 = g2*gpl, g4 = g2*g2;
                    float q2 = gmi*gmi, q3 = q2*gmi, q4 = q2*q2;
                    const float* wp = s_wx + oc*40 + j;
                    float s_ = wp[4]
                        + C1 *(wp[5]*gpl + wp[3]*gmi)
                        + C4 *(wp[6]*g2  + wp[2]*q2)
                        + C9 *(wp[7]*g3  + wp[1]*q3)
                        + C16*(wp[8]*g4  + wp[0]*q4);
                    g_fu[((nb*FEATS + oc)*PH + gy)*FUP + gx] = E0 * s_;
                }
            }
        }
    }
}

// ---------------- K3: transposed conv via tf32 MMA (global B, high occ) ----
// out[Y,X] = sum_j PS_j[Y,X+j];  PS_j: GEMM K=(oc,ky,q)=32*11*3, N=8=(comp,j)
#define CTW 29
__global__ __launch_bounds__(256) void kconvT_mma(){
    __shared__ float s_G[26*40];        // per-oc fu tile (tf32)
    __shared__ float s_PS[4640];        // shifted partial sums
    __shared__ int   s_off[40];

    int nb = blockIdx.z;
    int x0 = blockIdx.x * CTW, y0 = blockIdx.y * 16;
    int tid = threadIdx.x;
    int lane = tid & 31, warp = tid >> 5;
    int grp  = lane >> 2, four = lane & 3;

    for (int i = tid; i < 40; i += 256)
        s_off[i] = (i < 33) ? ((i/3)*40 + (i%3)*4) : 0;

    int pb[4][2];
    #pragma unroll
    for (int m = 0; m < 4; m++){
        int p0 = warp*64 + m*16 + grp;
        pb[m][0] = (p0 >> 5)*40 + (p0 & 31);
        int p1 = p0 + 8;
        pb[m][1] = (p1 >> 5)*40 + (p1 & 31);
    }

    float acc[4][4];
    #pragma unroll
    for (int m = 0; m < 4; m++)
        #pragma unroll
        for (int r = 0; r < 4; r++) acc[m][r] = 0.f;

    #pragma unroll 1
    for (int oc = 0; oc < FEATS; oc++){
        __syncthreads();
        const float* fup = g_fu + (nb*FEATS + oc)*PH*FUP;
        for (int i = tid; i < 26*40; i += 256){
            int r = i / 40, c = i - r*40;
            int gr = y0 + 6 + r, gc = x0 + 6 + c;
            s_G[i] = (gc < FUP) ? to_tf32(fup[gr*FUP + gc]) : 0.f;
        }
        __syncthreads();

        const float* Boc = g_Bt + oc*320;
        #pragma unroll
        for (int ks = 0; ks < 5; ks++){
            int k0 = ks*8 + four, k1 = k0 + 4;
            int o0 = s_off[k0], o1 = s_off[k1];
            unsigned b[2];
            b[0] = __float_as_uint(__ldg(Boc + k0*8 + grp));
            b[1] = __float_as_uint(__ldg(Boc + k1*8 + grp));
            #pragma unroll
            for (int m = 0; m < 4; m++){
                unsigned a[4];
                a[0] = __float_as_uint(s_G[pb[m][0] + o0]);
                a[1] = __float_as_uint(s_G[pb[m][1] + o0]);
                a[2] = __float_as_uint(s_G[pb[m][0] + o1]);
                a[3] = __float_as_uint(s_G[pb[m][1] + o1]);
                mma_tf32(acc[m], a, b);
            }
        }
    }

    // combine shifted partial sums through smem
    __syncthreads();
    #pragma unroll
    for (int m = 0; m < 4; m++){
        #pragma unroll
        for (int r2 = 0; r2 < 4; r2++){
            int p = warp*64 + m*16 + grp + ((r2 >> 1) << 3);
            int n = (four << 1) + (r2 & 1);
            s_PS[p*9 + n] = acc[m][r2];
        }
    }
    __syncthreads();

    const float inv = 1.f / (float)FEATS;
    for (int i = tid; i < 512; i += 256){
        int row = i >> 5, col = i & 31;
        int X = x0 + col, Y = y0 + row;
        if (col < CTW && X < HH){
            float orr = 0.f, oii = 0.f;
            #pragma unroll
            for (int j = 0; j < 4; j++){
                orr += s_PS[(i + j)*9 + j];
                oii += s_PS[(i + j)*9 + 4 + j];
            }
            g_ru[(nb*HH + Y)*HH + X] = make_float2(orr*inv, oii*inv);
        }
    }
}

// ---------------- D1: row forward FFT of s*(u*coil) ------------------------
__global__ __launch_bounds__(320) void kfft_row_fwd(const float* __restrict__ u,
                                                    const float* __restrict__ coil){
    __shared__ float2 SA[4][320], SB[4][320];
    int b    = blockIdx.x;
    int ygrp = b % 80;
    int nc   = b / 80;
    int c    = nc % NC, n = nc / NC;
    int t    = threadIdx.x;
    int line = t / 80, lt = t % 80;
    int y    = ygrp*4 + line;

    const float2* up = (const float2*)u    + (n*HH + y)*HH;
    const float2* cp = (const float2*)coil + ((n*NC + c)*HH + y)*HH;
    #pragma unroll
    for (int j = 0; j < 4; j++){
        int x = lt + 80*j;
        float2 v = cmul(up[x], cp[x]);
        float sg = ((x + y) & 1) ? -1.f : 1.f;
        SA[line][x] = make_float2(v.x*sg, v.y*sg);
    }
    __syncthreads();
    fft320(SA[line], SB[line], lt, -1.f);

    float2* dst = g_ks + ((n*NC + c)*HH + y)*HH;
    #pragma unroll
    for (int j = 0; j < 4; j++){ int x = lt + 80*j; dst[x] = SA[line][x]; }
}

// ---------------- D2: column fwd FFT + mask/subtract + column inv FFT ------
__global__ __launch_bounds__(320) void kfft_col(const float* __restrict__ f,
                                                const float* __restrict__ mask){
    __shared__ float2 SA[4][320], SB[4][320];
    int b    = blockIdx.x;
    int xgrp = b % 80;
    int nc   = b / 80;
    int c    = nc % NC, n = nc / NC;
    int t    = threadIdx.x;
    int line = t & 3, lt = t >> 2;
    int x    = xgrp*4 + line;

    float2* col = g_ks + (n*NC + c)*HH*HH + x;
    #pragma unroll
    for (int j = 0; j < 4; j++){ int y = lt + 80*j; SA[line][y] = col[y*HH]; }
    __syncthreads();
    fft320(SA[line], SB[line], lt, -1.f);

    const float sc = 1.f / 320.f;
    #pragma unroll
    for (int j = 0; j < 4; j++){
        int ky = lt + 80*j;
        float2 V = SA[line][ky];
        float  m = mask[(n*HH + ky)*HH + x];
        float2 fv = ((const float2*)f)[((n*NC + c)*HH + ky)*HH + x];
        float sg = ((ky + x) & 1) ? -1.f : 1.f;
        float wx = m * (V.x*sc - sg*fv.x);
        float wy = m * (V.y*sc - sg*fv.y);
        SA[line][ky] = make_float2(wx*sc, wy*sc);
    }
    __syncthreads();
    fft320(SA[line], SB[line], lt, 1.f);
    #pragma unroll
    for (int j = 0; j < 4; j++){ int y = lt + 80*j; col[y*HH] = SA[line][y]; }
}

// ---------------- D3a: row inverse FFT of g_ks in place --------------------
__global__ __launch_bounds__(320) void kfft_row_inv_a(){
    __shared__ float2 SA[4][320], SB[4][320];
    int b    = blockIdx.x;
    int ygrp = b % 80;
    int nc   = b / 80;
    int c    = nc % NC, n = nc / NC;
    int t    = threadIdx.x;
    int line = t / 80, lt = t % 80;
    int y    = ygrp*4 + line;

    float2* row = g_ks + ((n*NC + c)*HH + y)*HH;
    #pragma unroll
    for (int j = 0; j < 4; j++){ int x = lt + 80*j; SA[line][x] = row[x]; }
    __syncthreads();
    fft320(SA[line], SB[line], lt, 1.f);
    #pragma unroll
    for (int j = 0; j < 4; j++){ int x = lt + 80*j; row[x] = SA[line][x]; }
}

// ---------------- D3b: coil combine + final output -------------------------
__global__ void kcombine(const float* __restrict__ u,
                         const float* __restrict__ coil,
                         const float* __restrict__ lamb,
                         float* __restrict__ outp){
    int idx = blockIdx.x * blockDim.x + threadIdx.x;
    if (idx >= NB*HH*HH) return;
    int n = idx / (HH*HH);
    int r = idx % (HH*HH);
    int y = r / HH, x = r % HH;

    float ax = 0.f, ay = 0.f;
    const float2* ks = g_ks + n*NC*HH*HH + r;
    const float2* cp = (const float2*)coil + n*NC*HH*HH + r;
    #pragma unroll 5
    for (int c = 0; c < NC; c++){
        float2 w2 = ks[c*HH*HH];
        float2 cc = cp[c*HH*HH];
        ax += w2.x*cc.x + w2.y*cc.y;
        ay += w2.y*cc.x - w2.x*cc.y;
    }
    float sg  = ((x + y) & 1) ? -1.f : 1.f;
    float lam = lamb[0] * sg;
    float2 uv = ((const float2*)u)[idx];
    float2 rv = g_ru[idx];
    ((float2*)outp)[idx] = make_float2(uv.x - rv.x - lam*ax,
                                       uv.y - rv.y - lam*ay);
}

// ---------------- launch ---------------------------------------------------
extern "C" void kernel_launch(void* const* d_in, const int* in_sizes, int n_in,
                              void* d_out, int out_size){
    const float* u     = (const float*)d_in[0];   // (4,320,320,2)
    const float* f     = (const float*)d_in[1];   // (4,15,320,320,2)
    const float* coil  = (const float*)d_in[2];   // (4,15,320,320,2)
    const float* mask  = (const float*)d_in[3];   // (4,320,320)
    const float* ck    = (const float*)d_in[4];   // (32,1,11,11,2)
    const float* w_    = (const float*)d_in[5];   // (1,32,1,1,31)
    const float* mu_   = (const float*)d_in[6];   // (31,)
    const float* sig   = (const float*)d_in[7];   // (1,)
    const float* lamb  = (const float*)d_in[8];   // (1,)
    float* outp = (float*)d_out;

    kprep<<<(FEATS*40*8 + 255)/256, 256>>>(ck);
    kpad<<<(NB*UPD*UPD + 255)/256, 256>>>(u);
    kconv_mma<<<dim3(11, 22, NB), 256>>>(ck, w_, mu_, sig);
    kconvT_mma<<<dim3(12, 20, NB), 256>>>();
    kfft_row_fwd<<<NB*NC*80, 320>>>(u, coil);
    kfft_col<<<NB*NC*80, 320>>>(f, mask);
    kfft_row_inv_a<<<NB*NC*80, 320>>>();
    kcombine<<<(NB*HH*HH + 255)/256, 256>>>(u, coil, lamb, outp);
}

// round 14
// speedup vs baseline: 1.1040x; 1.0451x over previous
#include <cuda_runtime.h>
#include <cuda_bf16.h>

#define NB 4
#define NC 15
#define HH 320
#define FEATS 32
#define KS 11
#define KRBF 31
#define PH 342      // reflect-padded size (320 + 2*11)
#define UPD 352     // reflect + zero conv pad (342 + 2*5)
#define FUP 344     // pitch for f_u_k rows

// ---------------- static device scratch (no allocations allowed) ----------
__device__ float2 g_up[NB*UPD*UPD];          // (ur,ui) padded input
__device__ float  g_fu[NB*FEATS*PH*FUP];     // RBF(conv(u))
__device__ float2 g_ru[NB*HH*HH];            // regularizer output (cropped, /32)
__device__ float2 g_ks[NB*NC*HH*HH];         // k-space scratch
__device__ float  g_Bt[FEATS*40*8];          // convT tf32 weights [oc][k(40)][n(8)]

// ---------------- complex helpers ----------------
__device__ __forceinline__ float2 cmul(float2 a, float2 b){
    return make_float2(fmaf(a.x, b.x, -a.y*b.y), fmaf(a.x, b.y, a.y*b.x));
}
__device__ __forceinline__ float2 cadd(float2 a, float2 b){
    return make_float2(a.x+b.x, a.y+b.y);
}
__device__ __forceinline__ float2 cexp_(float ang){
    float s, c; __sincosf(ang, &s, &c); return make_float2(c, s);
}

#define TWO_PI 6.28318530717958647692f

// ---------------- tf32 helpers --------------------------------------------
__device__ __forceinline__ float to_tf32(float x){
    float r; asm("cvt.rna.tf32.f32 %0, %1;" : "=f"(r) : "f"(x)); return r;
}
__device__ __forceinline__ void mma_tf32(float* d, const unsigned* a, const unsigned* b){
    asm volatile("mma.sync.aligned.m16n8k8.row.col.f32.tf32.tf32.f32 "
        "{%0,%1,%2,%3}, {%4,%5,%6,%7}, {%8,%9}, {%0,%1,%2,%3};"
        : "+f"(d[0]), "+f"(d[1]), "+f"(d[2]), "+f"(d[3])
        : "r"(a[0]), "r"(a[1]), "r"(a[2]), "r"(a[3]), "r"(b[0]), "r"(b[1]));
}

// ---------------- 320-point Stockham FFT (radix 5*4*4*4) ------------------
__device__ __forceinline__ void r4stage(const float2* __restrict__ src,
                                        float2* __restrict__ dst,
                                        int lt, int S, int M, int NN, float ds){
    int q = lt % S;
    int p = lt / S;            // p < M
    float2 a0 = src[q + S*p];
    float2 a1 = src[q + S*(p +   M)];
    float2 a2 = src[q + S*(p + 2*M)];
    float2 a3 = src[q + S*(p + 3*M)];
    float2 t0 = make_float2(a0.x+a2.x, a0.y+a2.y);
    float2 t1 = make_float2(a0.x-a2.x, a0.y-a2.y);
    float2 t2 = make_float2(a1.x+a3.x, a1.y+a3.y);
    float2 t3 = make_float2(a1.x-a3.x, a1.y-a3.y);
    float2 it3 = make_float2(-ds*t3.y, ds*t3.x);   // ds*i*t3
    float2 c0 = make_float2(t0.x+t2.x, t0.y+t2.y);
    float2 c2 = make_float2(t0.x-t2.x, t0.y-t2.y);
    float2 c1 = make_float2(t1.x+it3.x, t1.y+it3.y);
    float2 c3 = make_float2(t1.x-it3.x, t1.y-it3.y);
    float base = ds * TWO_PI * (float)p / (float)NN;
    dst[q + S*(4*p + 0)] = c0;
    dst[q + S*(4*p + 1)] = cmul(c1, cexp_(base));
    dst[q + S*(4*p + 2)] = cmul(c2, cexp_(base*2.f));
    dst[q + S*(4*p + 3)] = cmul(c3, cexp_(base*3.f));
}

__device__ void fft320(float2* __restrict__ A, float2* __restrict__ B,
                       int lt, float ds){
    if (lt < 64){
        int p = lt;
        float2 a0 = A[p], a1 = A[p+64], a2 = A[p+128], a3 = A[p+192], a4 = A[p+256];
        B[5*p] = cadd(cadd(cadd(a0,a1), cadd(a2,a3)), a4);
        #pragma unroll
        for (int k = 1; k < 5; k++){
            float2 w1 = cexp_(ds * TWO_PI * 0.2f * (float)k);
            float2 wj = w1;
            float2 c = a0;
            c = cadd(c, cmul(a1, wj)); wj = cmul(wj, w1);
            c = cadd(c, cmul(a2, wj)); wj = cmul(wj, w1);
            c = cadd(c, cmul(a3, wj)); wj = cmul(wj, w1);
            c = cadd(c, cmul(a4, wj));
            float2 tw = cexp_(ds * TWO_PI * (float)(p*k) / 320.0f);
            B[5*p + k] = cmul(c, tw);
        }
    }
    __syncthreads();
    r4stage(B, A, lt,  5, 16, 64, ds);
    __syncthreads();
    r4stage(A, B, lt, 20,  4, 16, ds);
    __syncthreads();
    r4stage(B, A, lt, 80,  1,  4, ds);
    __syncthreads();
}

// ---------------- K0: precompute convT tf32 B matrix -----------------------
// k = ky*3+q (33 real, pad 40), n = comp*4+j; kx = 4q+j; flipped kernel.
__global__ void kprep(const float* __restrict__ ck){
    int i = blockIdx.x * 256 + threadIdx.x;
    if (i >= FEATS*40*8) return;
    int oc = i / 320;
    int r  = i - oc*320;
    int k  = r >> 3, n = r & 7;
    int ky = k / 3, q = k - ky*3;
    int comp = n >> 2, j = n & 3;
    int kx = 4*q + j;
    float v = 0.f;
    if (k < 33 && kx <= 10)
        v = to_tf32(ck[(oc*121 + (10-ky)*11 + (10-kx))*2 + comp]);
    g_Bt[i] = v;
}

// ---------------- K1: reflect + zero padding -------------------------------
__global__ void kpad(const float* __restrict__ u){
    int idx = blockIdx.x * blockDim.x + threadIdx.x;
    if (idx >= NB*UPD*UPD) return;
    int n  = idx / (UPD*UPD);
    int r  = idx % (UPD*UPD);
    int py = r / UPD, px = r % UPD;
    float2 v = make_float2(0.f, 0.f);
    if (!(py < 5 || py >= 347 || px < 5 || px >= 347)){
        int iy = py - 16, ix = px - 16;
        if (iy < 0) iy = -iy; else if (iy >= HH) iy = 2*HH - 2 - iy;
        if (ix < 0) ix = -ix; else if (ix >= HH) ix = 2*HH - 2 - ix;
        v = ((const float2*)u)[(n*HH + iy)*HH + ix];
    }
    g_up[idx] = v;
}

// ---------------- K2: fwd conv (2->32 ch) via tf32 MMA + fast RBF ----------
__global__ __launch_bounds__(256, 2) void kconv_mma(const float* __restrict__ ck,
                                                    const float* __restrict__ w_,
                                                    const float* __restrict__ mu_,
                                                    const float* __restrict__ sigma_){
    __shared__ float s_in[26*42*2];       // tf32-rounded input tile (float2 interleaved)
    __shared__ float s_B[248*34];         // tf32 weights [k][oc], pitch 34
    __shared__ int   s_off[248];          // im2col offsets (floats) per k
    __shared__ float s_wx[FEATS*40];      // RBF weights, zero-padded by 4 each side
    __shared__ float s_mu[KRBF];

    int nb = blockIdx.z;
    int x0 = blockIdx.x * 32, y0 = blockIdx.y * 16;
    int tid = threadIdx.x;

    for (int i = tid; i < 248; i += 256){
        int tap = i >> 1, comp = i & 1;
        int ky = tap / 11, kx = tap - ky*11;
        s_off[i] = (i < 242) ? ((ky*42 + kx)*2 + comp) : 0;
    }
    for (int i = tid; i < 248*32; i += 256){
        int k = i >> 5, oc = i & 31;
        s_B[k*34 + oc] = (k < 242) ? to_tf32(ck[oc*242 + k]) : 0.f;
    }
    for (int i = tid; i < FEATS*40; i += 256){
        int oc = i / 40, kk = i - oc*40;
        s_wx[i] = (kk >= 4 && kk < 4 + KRBF) ? w_[oc*KRBF + kk - 4] : 0.f;
    }
    if (tid < KRBF) s_mu[tid] = mu_[tid];
    const float2* up = g_up + nb*UPD*UPD;
    for (int i = tid; i < 26*42; i += 256){
        int r = i / 42, c = i - r*42;
        int y = y0 + r, x = x0 + c;
        float2 v = (y < UPD && x < UPD) ? up[y*UPD + x] : make_float2(0.f, 0.f);
        s_in[2*i]   = to_tf32(v.x);
        s_in[2*i+1] = to_tf32(v.y);
    }
    __syncthreads();

    int lane = tid & 31, warp = tid >> 5;
    int grp  = lane >> 2, four = lane & 3;

    int pb[4][2];
    #pragma unroll
    for (int m = 0; m < 4; m++){
        int p0 = warp*64 + m*16 + grp;
        pb[m][0] = ((p0 >> 5)*42 + (p0 & 31))*2;
        int p1 = p0 + 8;
        pb[m][1] = ((p1 >> 5)*42 + (p1 & 31))*2;
    }

    float acc[4][4][4];
    #pragma unroll
    for (int m = 0; m < 4; m++)
        #pragma unroll
        for (int n = 0; n < 4; n++)
            #pragma unroll
            for (int r = 0; r < 4; r++) acc[m][n][r] = 0.f;

    #pragma unroll 1
    for (int kc = 0; kc < 31; kc++){
        int kk = kc*8 + four;
        int o0 = s_off[kk], o1 = s_off[kk + 4];
        unsigned a[4][4];
        #pragma unroll
        for (int m = 0; m < 4; m++){
            a[m][0] = __float_as_uint(s_in[pb[m][0] + o0]);
            a[m][1] = __float_as_uint(s_in[pb[m][1] + o0]);
            a[m][2] = __float_as_uint(s_in[pb[m][0] + o1]);
            a[m][3] = __float_as_uint(s_in[pb[m][1] + o1]);
        }
        unsigned b[4][2];
        #pragma unroll
        for (int n = 0; n < 4; n++){
            b[n][0] = __float_as_uint(s_B[kk*34       + n*8 + grp]);
            b[n][1] = __float_as_uint(s_B[(kk+4)*34   + n*8 + grp]);
        }
        #pragma unroll
        for (int m = 0; m < 4; m++)
            #pragma unroll
            for (int n = 0; n < 4; n++)
                mma_tf32(acc[m][n], a[m], b[n]);
    }

    // ---- epilogue: factored RBF + store ----
    float sg    = sigma_[0];
    float h     = 0.5f / (sg * sg);
    float mu0   = s_mu[0];
    float delta = s_mu[1] - s_mu[0];
    float idel  = 1.f / delta;
    float c2    = 2.f * h * delta;
    float C1    = __expf(-h * delta * delta);
    float C1_2  = C1*C1;
    float C4    = C1_2*C1_2;
    float C8    = C4*C4;
    float C16   = C8*C8;
    float C9    = C8*C1;
    float tmax  = 10.f / (h * delta);

    #pragma unroll
    for (int m = 0; m < 4; m++){
        #pragma unroll
        for (int n = 0; n < 4; n++){
            #pragma unroll
            for (int r2 = 0; r2 < 4; r2++){
                int row = grp + ((r2 >> 1) << 3);
                int col = (four << 1) + (r2 & 1);
                int p  = warp*64 + m*16 + row;
                int gy = y0 + (p >> 5), gx = x0 + (p & 31);
                if (gy < PH && gx < PH){
                    int oc = n*8 + col;
                    float v = acc[m][n][r2];
                    int j = __float2int_rn((v - mu0) * idel);
                    j = max(0, min(KRBF-1, j));
                    float t = v - fmaf((float)j, delta, mu0);
                    t = fminf(fmaxf(t, -tmax), tmax);
                    float E0 = __expf(-h*t*t);
                    float gpl = __expf(c2*t);
                    float gmi = __expf(-c2*t);
                    float g2 = gpl*gpl, g3 = g2*gpl, g4 = g2*g2;
                    float q2 = gmi*gmi, q3 = q2*gmi, q4 = q2*q2;
                    const float* wp = s_wx + oc*40 + j;
                    float s_ = wp[4]
                        + C1 *(wp[5]*gpl + wp[3]*gmi)
                        + C4 *(wp[6]*g2  + wp[2]*q2)
                        + C9 *(wp[7]*g3  + wp[1]*q3)
                        + C16*(wp[8]*g4  + wp[0]*q4);
                    g_fu[((nb*FEATS + oc)*PH + gy)*FUP + gx] = E0 * s_;
                }
            }
        }
    }
}

// ---------------- K3: transposed conv, tf32 MMA, double-buffered oc loop ---
// out[Y,X] = sum_j PS_j[Y,X+j];  PS_j: GEMM K=(oc,ky,q)=32*11*3, N=8=(comp,j)
#define CTW 29
__global__ __launch_bounds__(256) void kconvT_mma(){
    __shared__ float s_G[2][26*40];     // double-buffered per-oc fu tile (tf32)
    __shared__ float s_PS[4640];        // shifted partial sums
    __shared__ int   s_off[40];

    int nb = blockIdx.z;
    int x0 = blockIdx.x * CTW, y0 = blockIdx.y * 16;
    int tid = threadIdx.x;
    int lane = tid & 31, warp = tid >> 5;
    int grp  = lane >> 2, four = lane & 3;

    for (int i = tid; i < 40; i += 256)
        s_off[i] = (i < 33) ? ((i/3)*40 + (i%3)*4) : 0;

    // initial fill: oc = 0 into buffer 0
    {
        const float* fup = g_fu + (nb*FEATS + 0)*PH*FUP;
        for (int i = tid; i < 26*40; i += 256){
            int r = i / 40, c = i - r*40;
            int gr = y0 + 6 + r, gc = x0 + 6 + c;
            s_G[0][i] = (gc < FUP) ? to_tf32(fup[gr*FUP + gc]) : 0.f;
        }
    }

    int pb[4][2];
    #pragma unroll
    for (int m = 0; m < 4; m++){
        int p0 = warp*64 + m*16 + grp;
        pb[m][0] = (p0 >> 5)*40 + (p0 & 31);
        int p1 = p0 + 8;
        pb[m][1] = (p1 >> 5)*40 + (p1 & 31);
    }

    float acc[4][4];
    #pragma unroll
    for (int m = 0; m < 4; m++)
        #pragma unroll
        for (int r = 0; r < 4; r++) acc[m][r] = 0.f;

    __syncthreads();

    #pragma unroll 1
    for (int oc = 0; oc < FEATS; oc++){
        int cur = oc & 1;

        // 1) issue prefetch LDGs for oc+1 (latency hidden by mma below)
        float pf[5];
        if (oc + 1 < FEATS){
            const float* fup = g_fu + (nb*FEATS + oc + 1)*PH*FUP;
            int idx = 0;
            for (int i = tid; i < 26*40; i += 256, idx++){
                int r = i / 40, c = i - r*40;
                int gr = y0 + 6 + r, gc = x0 + 6 + c;
                pf[idx] = (gc < FUP) ? fup[gr*FUP + gc] : 0.f;
            }
        }

        // 2) hoist all B fragments for this oc
        const float* Boc = g_Bt + oc*320;
        unsigned breg[5][2];
        #pragma unroll
        for (int ks = 0; ks < 5; ks++){
            int k0 = ks*8 + four, k1 = k0 + 4;
            breg[ks][0] = __float_as_uint(__ldg(Boc + k0*8 + grp));
            breg[ks][1] = __float_as_uint(__ldg(Boc + k1*8 + grp));
        }

        // 3) mma on current buffer
        const float* G = s_G[cur];
        #pragma unroll
        for (int ks = 0; ks < 5; ks++){
            int k0 = ks*8 + four, k1 = k0 + 4;
            int o0 = s_off[k0], o1 = s_off[k1];
            #pragma unroll
            for (int m = 0; m < 4; m++){
                unsigned a[4];
                a[0] = __float_as_uint(G[pb[m][0] + o0]);
                a[1] = __float_as_uint(G[pb[m][1] + o0]);
                a[2] = __float_as_uint(G[pb[m][0] + o1]);
                a[3] = __float_as_uint(G[pb[m][1] + o1]);
                mma_tf32(acc[m], a, breg[ks]);
            }
        }

        // 4) commit prefetch to the other buffer; single sync per oc
        if (oc + 1 < FEATS){
            int idx = 0;
            for (int i = tid; i < 26*40; i += 256, idx++)
                s_G[1 - cur][i] = to_tf32(pf[idx]);
        }
        __syncthreads();
    }

    // combine shifted partial sums through smem
    #pragma unroll
    for (int m = 0; m < 4; m++){
        #pragma unroll
        for (int r2 = 0; r2 < 4; r2++){
            int p = warp*64 + m*16 + grp + ((r2 >> 1) << 3);
            int n = (four << 1) + (r2 & 1);
            s_PS[p*9 + n] = acc[m][r2];
        }
    }
    __syncthreads();

    const float inv = 1.f / (float)FEATS;
    for (int i = tid; i < 512; i += 256){
        int row = i >> 5, col = i & 31;
        int X = x0 + col, Y = y0 + row;
        if (col < CTW && X < HH){
            float orr = 0.f, oii = 0.f;
            #pragma unroll
            for (int j = 0; j < 4; j++){
                orr += s_PS[(i + j)*9 + j];
                oii += s_PS[(i + j)*9 + 4 + j];
            }
            g_ru[(nb*HH + Y)*HH + X] = make_float2(orr*inv, oii*inv);
        }
    }
}

// ---------------- D1: row forward FFT of s*(u*coil) ------------------------
__global__ __launch_bounds__(320) void kfft_row_fwd(const float* __restrict__ u,
                                                    const float* __restrict__ coil){
    __shared__ float2 SA[4][320], SB[4][320];
    int b    = blockIdx.x;
    int ygrp = b % 80;
    int nc   = b / 80;
    int c    = nc % NC, n = nc / NC;
    int t    = threadIdx.x;
    int line = t / 80, lt = t % 80;
    int y    = ygrp*4 + line;

    const float2* up = (const float2*)u    + (n*HH + y)*HH;
    const float2* cp = (const float2*)coil + ((n*NC + c)*HH + y)*HH;
    #pragma unroll
    for (int j = 0; j < 4; j++){
        int x = lt + 80*j;
        float2 v = cmul(up[x], cp[x]);
        float sg = ((x + y) & 1) ? -1.f : 1.f;
        SA[line][x] = make_float2(v.x*sg, v.y*sg);
    }
    __syncthreads();
    fft320(SA[line], SB[line], lt, -1.f);

    float2* dst = g_ks + ((n*NC + c)*HH + y)*HH;
    #pragma unroll
    for (int j = 0; j < 4; j++){ int x = lt + 80*j; dst[x] = SA[line][x]; }
}

// ---------------- D2: column fwd FFT + mask/subtract + column inv FFT ------
__global__ __launch_bounds__(320) void kfft_col(const float* __restrict__ f,
                                                const float* __restrict__ mask){
    __shared__ float2 SA[4][320], SB[4][320];
    int b    = blockIdx.x;
    int xgrp = b % 80;
    int nc   = b / 80;
    int c    = nc % NC, n = nc / NC;
    int t    = threadIdx.x;
    int line = t & 3, lt = t >> 2;
    int x    = xgrp*4 + line;

    float2* col = g_ks + (n*NC + c)*HH*HH + x;
    #pragma unroll
    for (int j = 0; j < 4; j++){ int y = lt + 80*j; SA[line][y] = col[y*HH]; }
    __syncthreads();
    fft320(SA[line], SB[line], lt, -1.f);

    const float sc = 1.f / 320.f;
    #pragma unroll
    for (int j = 0; j < 4; j++){
        int ky = lt + 80*j;
        float2 V = SA[line][ky];
        float  m = mask[(n*HH + ky)*HH + x];
        float2 fv = ((const float2*)f)[((n*NC + c)*HH + ky)*HH + x];
        float sg = ((ky + x) & 1) ? -1.f : 1.f;
        float wx = m * (V.x*sc - sg*fv.x);
        float wy = m * (V.y*sc - sg*fv.y);
        SA[line][ky] = make_float2(wx*sc, wy*sc);
    }
    __syncthreads();
    fft320(SA[line], SB[line], lt, 1.f);
    #pragma unroll
    for (int j = 0; j < 4; j++){ int y = lt + 80*j; col[y*HH] = SA[line][y]; }
}

// ---------------- D3a: row inverse FFT of g_ks in place --------------------
__global__ __launch_bounds__(320) void kfft_row_inv_a(){
    __shared__ float2 SA[4][320], SB[4][320];
    int b    = blockIdx.x;
    int ygrp = b % 80;
    int nc   = b / 80;
    int c    = nc % NC, n = nc / NC;
    int t    = threadIdx.x;
    int line = t / 80, lt = t % 80;
    int y    = ygrp*4 + line;

    float2* row = g_ks + ((n*NC + c)*HH + y)*HH;
    #pragma unroll
    for (int j = 0; j < 4; j++){ int x = lt + 80*j; SA[line][x] = row[x]; }
    __syncthreads();
    fft320(SA[line], SB[line], lt, 1.f);
    #pragma unroll
    for (int j = 0; j < 4; j++){ int x = lt + 80*j; row[x] = SA[line][x]; }
}

// ---------------- D3b: coil combine + final output -------------------------
__global__ void kcombine(const float* __restrict__ u,
                         const float* __restrict__ coil,
                         const float* __restrict__ lamb,
                         float* __restrict__ outp){
    int idx = blockIdx.x * blockDim.x + threadIdx.x;
    if (idx >= NB*HH*HH) return;
    int n = idx / (HH*HH);
    int r = idx % (HH*HH);
    int y = r / HH, x = r % HH;

    float ax = 0.f, ay = 0.f;
    const float2* ks = g_ks + n*NC*HH*HH + r;
    const float2* cp = (const float2*)coil + n*NC*HH*HH + r;
    #pragma unroll 5
    for (int c = 0; c < NC; c++){
        float2 w2 = ks[c*HH*HH];
        float2 cc = cp[c*HH*HH];
        ax += w2.x*cc.x + w2.y*cc.y;
        ay += w2.y*cc.x - w2.x*cc.y;
    }
    float sg  = ((x + y) & 1) ? -1.f : 1.f;
    float lam = lamb[0] * sg;
    float2 uv = ((const float2*)u)[idx];
    float2 rv = g_ru[idx];
    ((float2*)outp)[idx] = make_float2(uv.x - rv.x - lam*ax,
                                       uv.y - rv.y - lam*ay);
}

// ---------------- launch ---------------------------------------------------
extern "C" void kernel_launch(void* const* d_in, const int* in_sizes, int n_in,
                              void* d_out, int out_size){
    const float* u     = (const float*)d_in[0];   // (4,320,320,2)
    const float* f     = (const float*)d_in[1];   // (4,15,320,320,2)
    const float* coil  = (const float*)d_in[2];   // (4,15,320,320,2)
    const float* mask  = (const float*)d_in[3];   // (4,320,320)
    const float* ck    = (const float*)d_in[4];   // (32,1,11,11,2)
    const float* w_    = (const float*)d_in[5];   // (1,32,1,1,31)
    const float* mu_   = (const float*)d_in[6];   // (31,)
    const float* sig   = (const float*)d_in[7];   // (1,)
    const float* lamb  = (const float*)d_in[8];   // (1,)
    float* outp = (float*)d_out;

    kprep<<<(FEATS*40*8 + 255)/256, 256>>>(ck);
    kpad<<<(NB*UPD*UPD + 255)/256, 256>>>(u);
    kconv_mma<<<dim3(11, 22, NB), 256>>>(ck, w_, mu_, sig);
    kconvT_mma<<<dim3(12, 20, NB), 256>>>();
    kfft_row_fwd<<<NB*NC*80, 320>>>(u, coil);
    kfft_col<<<NB*NC*80, 320>>>(f, mask);
    kfft_row_inv_a<<<NB*NC*80, 320>>>();
    kcombine<<<(NB*HH*HH + 255)/256, 256>>>(u, coil, lamb, outp);
}

// round 16
// speedup vs baseline: 1.2007x; 1.0876x over previous
#include <cuda_runtime.h>
#include <cuda_bf16.h>
#include <cuda_fp16.h>

#define NB 4
#define NC 15
#define HH 320
#define FEATS 32
#define KS 11
#define KRBF 31
#define PH 342      // reflect-padded size (320 + 2*11)
#define UPD 352     // reflect + zero conv pad (342 + 2*5)
#define FUP 344     // pitch for f_u_k rows

// ---------------- static device scratch (no allocations allowed) ----------
__device__ float2 g_up[NB*UPD*UPD];          // (ur,ui) padded input
__device__ float  g_fu[NB*FEATS*PH*FUP];     // RBF(conv(u))
__device__ float2 g_ru[NB*HH*HH];            // regularizer partial (oc 0..15)
__device__ float2 g_ru2[NB*HH*HH];           // regularizer partial (oc 16..31)
__device__ float2 g_ks[NB*NC*HH*HH];         // k-space scratch
__device__ float  g_Bt[FEATS*40*8];          // convT tf32 weights [oc][k(40)][n(8)]

// ---------------- complex helpers ----------------
__device__ __forceinline__ float2 cmul(float2 a, float2 b){
    return make_float2(fmaf(a.x, b.x, -a.y*b.y), fmaf(a.x, b.y, a.y*b.x));
}
__device__ __forceinline__ float2 cadd(float2 a, float2 b){
    return make_float2(a.x+b.x, a.y+b.y);
}
__device__ __forceinline__ float2 cexp_(float ang){
    float s, c; __sincosf(ang, &s, &c); return make_float2(c, s);
}

#define TWO_PI 6.28318530717958647692f

// ---------------- mma helpers ----------------------------------------------
__device__ __forceinline__ float to_tf32(float x){
    float r; asm("cvt.rna.tf32.f32 %0, %1;" : "=f"(r) : "f"(x)); return r;
}
__device__ __forceinline__ void mma_tf32(float* d, const unsigned* a, const unsigned* b){
    asm volatile("mma.sync.aligned.m16n8k8.row.col.f32.tf32.tf32.f32 "
        "{%0,%1,%2,%3}, {%4,%5,%6,%7}, {%8,%9}, {%0,%1,%2,%3};"
        : "+f"(d[0]), "+f"(d[1]), "+f"(d[2]), "+f"(d[3])
        : "r"(a[0]), "r"(a[1]), "r"(a[2]), "r"(a[3]), "r"(b[0]), "r"(b[1]));
}
__device__ __forceinline__ unsigned pack_h2(float a, float b){
    __half2 h = __floats2half2_rn(a, b);
    return *reinterpret_cast<unsigned*>(&h);
}
__device__ __forceinline__ void mma_f16(float* d, const unsigned* a, const unsigned* b){
    asm volatile("mma.sync.aligned.m16n8k16.row.col.f32.f16.f16.f32 "
        "{%0,%1,%2,%3}, {%4,%5,%6,%7}, {%8,%9}, {%0,%1,%2,%3};"
        : "+f"(d[0]), "+f"(d[1]), "+f"(d[2]), "+f"(d[3])
        : "r"(a[0]), "r"(a[1]), "r"(a[2]), "r"(a[3]), "r"(b[0]), "r"(b[1]));
}

// ---------------- 320-point Stockham FFT (radix 5*4*4*4) ------------------
__device__ __forceinline__ void r4stage(const float2* __restrict__ src,
                                        float2* __restrict__ dst,
                                        int lt, int S, int M, int NN, float ds){
    int q = lt % S;
    int p = lt / S;            // p < M
    float2 a0 = src[q + S*p];
    float2 a1 = src[q + S*(p +   M)];
    float2 a2 = src[q + S*(p + 2*M)];
    float2 a3 = src[q + S*(p + 3*M)];
    float2 t0 = make_float2(a0.x+a2.x, a0.y+a2.y);
    float2 t1 = make_float2(a0.x-a2.x, a0.y-a2.y);
    float2 t2 = make_float2(a1.x+a3.x, a1.y+a3.y);
    float2 t3 = make_float2(a1.x-a3.x, a1.y-a3.y);
    float2 it3 = make_float2(-ds*t3.y, ds*t3.x);   // ds*i*t3
    float2 c0 = make_float2(t0.x+t2.x, t0.y+t2.y);
    float2 c2 = make_float2(t0.x-t2.x, t0.y-t2.y);
    float2 c1 = make_float2(t1.x+it3.x, t1.y+it3.y);
    float2 c3 = make_float2(t1.x-it3.x, t1.y-it3.y);
    float base = ds * TWO_PI * (float)p / (float)NN;
    dst[q + S*(4*p + 0)] = c0;
    dst[q + S*(4*p + 1)] = cmul(c1, cexp_(base));
    dst[q + S*(4*p + 2)] = cmul(c2, cexp_(base*2.f));
    dst[q + S*(4*p + 3)] = cmul(c3, cexp_(base*3.f));
}

__device__ void fft320(float2* __restrict__ A, float2* __restrict__ B,
                       int lt, float ds){
    if (lt < 64){
        int p = lt;
        float2 a0 = A[p], a1 = A[p+64], a2 = A[p+128], a3 = A[p+192], a4 = A[p+256];
        B[5*p] = cadd(cadd(cadd(a0,a1), cadd(a2,a3)), a4);
        #pragma unroll
        for (int k = 1; k < 5; k++){
            float2 w1 = cexp_(ds * TWO_PI * 0.2f * (float)k);
            float2 wj = w1;
            float2 c = a0;
            c = cadd(c, cmul(a1, wj)); wj = cmul(wj, w1);
            c = cadd(c, cmul(a2, wj)); wj = cmul(wj, w1);
            c = cadd(c, cmul(a3, wj)); wj = cmul(wj, w1);
            c = cadd(c, cmul(a4, wj));
            float2 tw = cexp_(ds * TWO_PI * (float)(p*k) / 320.0f);
            B[5*p + k] = cmul(c, tw);
        }
    }
    __syncthreads();
    r4stage(B, A, lt,  5, 16, 64, ds);
    __syncthreads();
    r4stage(A, B, lt, 20,  4, 16, ds);
    __syncthreads();
    r4stage(B, A, lt, 80,  1,  4, ds);
    __syncthreads();
}

// ---------------- K0: precompute convT tf32 B matrix -----------------------
__global__ void kprep(const float* __restrict__ ck){
    int i = blockIdx.x * 256 + threadIdx.x;
    if (i >= FEATS*40*8) return;
    int oc = i / 320;
    int r  = i - oc*320;
    int k  = r >> 3, n = r & 7;
    int ky = k / 3, q = k - ky*3;
    int comp = n >> 2, j = n & 3;
    int kx = 4*q + j;
    float v = 0.f;
    if (k < 33 && kx <= 10)
        v = to_tf32(ck[(oc*121 + (10-ky)*11 + (10-kx))*2 + comp]);
    g_Bt[i] = v;
}

// ---------------- K1: reflect + zero padding -------------------------------
__global__ void kpad(const float* __restrict__ u){
    int idx = blockIdx.x * blockDim.x + threadIdx.x;
    if (idx >= NB*UPD*UPD) return;
    int n  = idx / (UPD*UPD);
    int r  = idx % (UPD*UPD);
    int py = r / UPD, px = r % UPD;
    float2 v = make_float2(0.f, 0.f);
    if (!(py < 5 || py >= 347 || px < 5 || px >= 347)){
        int iy = py - 16, ix = px - 16;
        if (iy < 0) iy = -iy; else if (iy >= HH) iy = 2*HH - 2 - iy;
        if (ix < 0) ix = -ix; else if (ix >= HH) ix = 2*HH - 2 - ix;
        v = ((const float2*)u)[(n*HH + iy)*HH + ix];
    }
    g_up[idx] = v;
}

// ---------------- K2: fwd conv (2->32 ch) via fp16 MMA + fast RBF ----------
// K: 121 taps (re,im packed as half2 k-pairs) padded to 128 -> 16 mma steps.
__global__ __launch_bounds__(256, 2) void kconv_mma(const float* __restrict__ ck,
                                                    const float* __restrict__ w_,
                                                    const float* __restrict__ mu_,
                                                    const float* __restrict__ sigma_){
    __shared__ unsigned s_in[26*42];      // half2 (re,im) input tile
    __shared__ unsigned s_B[128*40];      // half2 (wr,wi) [tap][oc], pitch 40
    __shared__ int   s_off[128];          // per-tap offset into s_in (half2 units)
    __shared__ float s_wx[FEATS*40];      // RBF weights, zero-padded by 4 each side
    __shared__ float s_mu[KRBF];

    int nb = blockIdx.z;
    int x0 = blockIdx.x * 32, y0 = blockIdx.y * 16;
    int tid = threadIdx.x;

    for (int i = tid; i < 128; i += 256){
        int ky = i / 11, kx = i - ky*11;
        s_off[i] = (i < 121) ? (ky*42 + kx) : 0;
    }
    for (int i = tid; i < 128*32; i += 256){
        int tap = i >> 5, oc = i & 31;
        unsigned v = 0u;
        if (tap < 121)
            v = pack_h2(ck[oc*242 + tap*2], ck[oc*242 + tap*2 + 1]);
        s_B[tap*40 + oc] = v;
    }
    for (int i = tid; i < FEATS*40; i += 256){
        int oc = i / 40, kk = i - oc*40;
        s_wx[i] = (kk >= 4 && kk < 4 + KRBF) ? w_[oc*KRBF + kk - 4] : 0.f;
    }
    if (tid < KRBF) s_mu[tid] = mu_[tid];
    const float2* up = g_up + nb*UPD*UPD;
    for (int i = tid; i < 26*42; i += 256){
        int r = i / 42, c = i - r*42;
        int y = y0 + r, x = x0 + c;
        float2 v = (y < UPD && x < UPD) ? up[y*UPD + x] : make_float2(0.f, 0.f);
        s_in[i] = pack_h2(v.x, v.y);
    }
    __syncthreads();

    int lane = tid & 31, warp = tid >> 5;
    int grp  = lane >> 2, four = lane & 3;

    int pb[4][2];
    #pragma unroll
    for (int m = 0; m < 4; m++){
        int p0 = warp*64 + m*16 + grp;
        pb[m][0] = (p0 >> 5)*42 + (p0 & 31);
        int p1 = p0 + 8;
        pb[m][1] = (p1 >> 5)*42 + (p1 & 31);
    }

    float acc[4][4][4];
    #pragma unroll
    for (int m = 0; m < 4; m++)
        #pragma unroll
        for (int n = 0; n < 4; n++)
            #pragma unroll
            for (int r = 0; r < 4; r++) acc[m][n][r] = 0.f;

    #pragma unroll 1
    for (int s = 0; s < 16; s++){
        int t0 = s*8 + four, t1 = t0 + 4;
        int o0 = s_off[t0], o1 = s_off[t1];
        unsigned a[4][4];
        #pragma unroll
        for (int m = 0; m < 4; m++){
            a[m][0] = s_in[pb[m][0] + o0];
            a[m][1] = s_in[pb[m][1] + o0];
            a[m][2] = s_in[pb[m][0] + o1];
            a[m][3] = s_in[pb[m][1] + o1];
        }
        unsigned b[4][2];
        #pragma unroll
        for (int n = 0; n < 4; n++){
            b[n][0] = s_B[t0*40 + n*8 + grp];
            b[n][1] = s_B[t1*40 + n*8 + grp];
        }
        #pragma unroll
        for (int m = 0; m < 4; m++)
            #pragma unroll
            for (int n = 0; n < 4; n++)
                mma_f16(acc[m][n], a[m], b[n]);
    }

    // ---- epilogue: factored RBF + store ----
    float sg    = sigma_[0];
    float h     = 0.5f / (sg * sg);
    float mu0   = s_mu[0];
    float delta = s_mu[1] - s_mu[0];
    float idel  = 1.f / delta;
    float c2    = 2.f * h * delta;
    float C1    = __expf(-h * delta * delta);
    float C1_2  = C1*C1;
    float C4    = C1_2*C1_2;
    float C8    = C4*C4;
    float C16   = C8*C8;
    float C9    = C8*C1;
    float tmax  = 10.f / (h * delta);

    #pragma unroll
    for (int m = 0; m < 4; m++){
        #pragma unroll
        for (int n = 0; n < 4; n++){
            #pragma unroll
            for (int r2 = 0; r2 < 4; r2++){
                int row = grp + ((r2 >> 1) << 3);
                int col = (four << 1) + (r2 & 1);
                int p  = warp*64 + m*16 + row;
                int gy = y0 + (p >> 5), gx = x0 + (p & 31);
                if (gy < PH && gx < PH){
                    int oc = n*8 + col;
                    float v = acc[m][n][r2];
                    int j = __float2int_rn((v - mu0) * idel);
                    j = max(0, min(KRBF-1, j));
                    float t = v - fmaf((float)j, delta, mu0);
                    t = fminf(fmaxf(t, -tmax), tmax);
                    float E0 = __expf(-h*t*t);
                    float gpl = __expf(c2*t);
                    float gmi = __expf(-c2*t);
                    float g2 = gpl*gpl, g3 = g2*gpl, g4 = g2*g2;
                    float q2 = gmi*gmi, q3 = q2*gmi, q4 = q2*q2;
                    const float* wp = s_wx + oc*40 + j;
                    float s_ = wp[4]
                        + C1 *(wp[5]*gpl + wp[3]*gmi)
                        + C4 *(wp[6]*g2  + wp[2]*q2)
                        + C9 *(wp[7]*g3  + wp[1]*q3)
                        + C16*(wp[8]*g4  + wp[0]*q4);
                    g_fu[((nb*FEATS + oc)*PH + gy)*FUP + gx] = E0 * s_;
                }
            }
        }
    }
}

// ---------------- K3: transposed conv, tf32 MMA, double-buffered, split-K --
// Each block handles 16 oc; half 0 -> g_ru, half 1 -> g_ru2.
#define CTW 29
__global__ __launch_bounds__(256) void kconvT_mma(){
    __shared__ float s_G[2][26*40];     // double-buffered per-oc fu tile (tf32)
    __shared__ float s_PS[4640];        // shifted partial sums
    __shared__ int   s_off[40];

    int zz = blockIdx.z;
    int nb = zz & 3, half = zz >> 2;
    int ocbase = half * 16;
    int x0 = blockIdx.x * CTW, y0 = blockIdx.y * 16;
    int tid = threadIdx.x;
    int lane = tid & 31, warp = tid >> 5;
    int grp  = lane >> 2, four = lane & 3;

    for (int i = tid; i < 40; i += 256)
        s_off[i] = (i < 33) ? ((i/3)*40 + (i%3)*4) : 0;

    // initial fill: oc = ocbase into buffer 0
    {
        const float* fup = g_fu + (nb*FEATS + ocbase)*PH*FUP;
        for (int i = tid; i < 26*40; i += 256){
            int r = i / 40, c = i - r*40;
            int gr = y0 + 6 + r, gc = x0 + 6 + c;
            s_G[0][i] = (gc < FUP) ? to_tf32(fup[gr*FUP + gc]) : 0.f;
        }
    }

    int pb[4][2];
    #pragma unroll
    for (int m = 0; m < 4; m++){
        int p0 = warp*64 + m*16 + grp;
        pb[m][0] = (p0 >> 5)*40 + (p0 & 31);
        int p1 = p0 + 8;
        pb[m][1] = (p1 >> 5)*40 + (p1 & 31);
    }

    float acc[4][4];
    #pragma unroll
    for (int m = 0; m < 4; m++)
        #pragma unroll
        for (int r = 0; r < 4; r++) acc[m][r] = 0.f;

    __syncthreads();

    #pragma unroll 1
    for (int t = 0; t < 16; t++){
        int oc  = ocbase + t;
        int cur = t & 1;

        // 1) prefetch LDGs for next oc (latency hidden by mma below)
        float pf[5];
        if (t + 1 < 16){
            const float* fup = g_fu + (nb*FEATS + oc + 1)*PH*FUP;
            int idx = 0;
            for (int i = tid; i < 26*40; i += 256, idx++){
                int r = i / 40, c = i - r*40;
                int gr = y0 + 6 + r, gc = x0 + 6 + c;
                pf[idx] = (gc < FUP) ? fup[gr*FUP + gc] : 0.f;
            }
        }

        // 2) hoist all B fragments for this oc
        const float* Boc = g_Bt + oc*320;
        unsigned breg[5][2];
        #pragma unroll
        for (int ks = 0; ks < 5; ks++){
            int k0 = ks*8 + four, k1 = k0 + 4;
            breg[ks][0] = __float_as_uint(__ldg(Boc + k0*8 + grp));
            breg[ks][1] = __float_as_uint(__ldg(Boc + k1*8 + grp));
        }

        // 3) mma on current buffer
        const float* G = s_G[cur];
        #pragma unroll
        for (int ks = 0; ks < 5; ks++){
            int k0 = ks*8 + four, k1 = k0 + 4;
            int o0 = s_off[k0], o1 = s_off[k1];
            #pragma unroll
            for (int m = 0; m < 4; m++){
                unsigned a[4];
                a[0] = __float_as_uint(G[pb[m][0] + o0]);
                a[1] = __float_as_uint(G[pb[m][1] + o0]);
                a[2] = __float_as_uint(G[pb[m][0] + o1]);
                a[3] = __float_as_uint(G[pb[m][1] + o1]);
                mma_tf32(acc[m], a, breg[ks]);
            }
        }

        // 4) commit prefetch to the other buffer; single sync per oc
        if (t + 1 < 16){
            int idx = 0;
            for (int i = tid; i < 26*40; i += 256, idx++)
                s_G[1 - cur][i] = to_tf32(pf[idx]);
        }
        __syncthreads();
    }

    // combine shifted partial sums through smem
    #pragma unroll
    for (int m = 0; m < 4; m++){
        #pragma unroll
        for (int r2 = 0; r2 < 4; r2++){
            int p = warp*64 + m*16 + grp + ((r2 >> 1) << 3);
            int n = (four << 1) + (r2 & 1);
            s_PS[p*9 + n] = acc[m][r2];
        }
    }
    __syncthreads();

    float2* dst = half ? g_ru2 : g_ru;
    const float inv = 1.f / (float)FEATS;
    for (int i = tid; i < 512; i += 256){
        int row = i >> 5, col = i & 31;
        int X = x0 + col, Y = y0 + row;
        if (col < CTW && X < HH){
            float orr = 0.f, oii = 0.f;
            #pragma unroll
            for (int j = 0; j < 4; j++){
                orr += s_PS[(i + j)*9 + j];
                oii += s_PS[(i + j)*9 + 4 + j];
            }
            dst[(nb*HH + Y)*HH + X] = make_float2(orr*inv, oii*inv);
        }
    }
}

// ---------------- D1: row forward FFT of s*(u*coil) ------------------------
__global__ __launch_bounds__(320) void kfft_row_fwd(const float* __restrict__ u,
                                                    const float* __restrict__ coil){
    __shared__ float2 SA[4][320], SB[4][320];
    int b    = blockIdx.x;
    int ygrp = b % 80;
    int nc   = b / 80;
    int c    = nc % NC, n = nc / NC;
    int t    = threadIdx.x;
    int line = t / 80, lt = t % 80;
    int y    = ygrp*4 + line;

    const float2* up = (const float2*)u    + (n*HH + y)*HH;
    const float2* cp = (const float2*)coil + ((n*NC + c)*HH + y)*HH;
    #pragma unroll
    for (int j = 0; j < 4; j++){
        int x = lt + 80*j;
        float2 v = cmul(up[x], cp[x]);
        float sg = ((x + y) & 1) ? -1.f : 1.f;
        SA[line][x] = make_float2(v.x*sg, v.y*sg);
    }
    __syncthreads();
    fft320(SA[line], SB[line], lt, -1.f);

    float2* dst = g_ks + ((n*NC + c)*HH + y)*HH;
    #pragma unroll
    for (int j = 0; j < 4; j++){ int x = lt + 80*j; dst[x] = SA[line][x]; }
}

// ---------------- D2: column fwd FFT + mask/subtract + column inv FFT ------
__global__ __launch_bounds__(320) void kfft_col(const float* __restrict__ f,
                                                const float* __restrict__ mask){
    __shared__ float2 SA[4][320], SB[4][320];
    int b    = blockIdx.x;
    int xgrp = b % 80;
    int nc   = b / 80;
    int c    = nc % NC, n = nc / NC;
    int t    = threadIdx.x;
    int line = t & 3, lt = t >> 2;
    int x    = xgrp*4 + line;

    float2* col = g_ks + (n*NC + c)*HH*HH + x;
    #pragma unroll
    for (int j = 0; j < 4; j++){ int y = lt + 80*j; SA[line][y] = col[y*HH]; }
    __syncthreads();
    fft320(SA[line], SB[line], lt, -1.f);

    const float sc = 1.f / 320.f;
    #pragma unroll
    for (int j = 0; j < 4; j++){
        int ky = lt + 80*j;
        float2 V = SA[line][ky];
        float  m = mask[(n*HH + ky)*HH + x];
        float2 fv = ((const float2*)f)[((n*NC + c)*HH + ky)*HH + x];
        float sg = ((ky + x) & 1) ? -1.f : 1.f;
        float wx = m * (V.x*sc - sg*fv.x);
        float wy = m * (V.y*sc - sg*fv.y);
        SA[line][ky] = make_float2(wx*sc, wy*sc);
    }
    __syncthreads();
    fft320(SA[line], SB[line], lt, 1.f);
    #pragma unroll
    for (int j = 0; j < 4; j++){ int y = lt + 80*j; col[y*HH] = SA[line][y]; }
}

// ---------------- D3a: row inverse FFT of g_ks in place --------------------
__global__ __launch_bounds__(320) void kfft_row_inv_a(){
    __shared__ float2 SA[4][320], SB[4][320];
    int b    = blockIdx.x;
    int ygrp = b % 80;
    int nc   = b / 80;
    int c    = nc % NC, n = nc / NC;
    int t    = threadIdx.x;
    int line = t / 80, lt = t % 80;
    int y    = ygrp*4 + line;

    float2* row = g_ks + ((n*NC + c)*HH + y)*HH;
    #pragma unroll
    for (int j = 0; j < 4; j++){ int x = lt + 80*j; SA[line][x] = row[x]; }
    __syncthreads();
    fft320(SA[line], SB[line], lt, 1.f);
    #pragma unroll
    for (int j = 0; j < 4; j++){ int x = lt + 80*j; row[x] = SA[line][x]; }
}

// ---------------- D3b: coil combine + final output -------------------------
__global__ void kcombine(const float* __restrict__ u,
                         const float* __restrict__ coil,
                         const float* __restrict__ lamb,
                         float* __restrict__ outp){
    int idx = blockIdx.x * blockDim.x + threadIdx.x;
    if (idx >= NB*HH*HH) return;
    int n = idx / (HH*HH);
    int r = idx % (HH*HH);
    int y = r / HH, x = r % HH;

    float ax = 0.f, ay = 0.f;
    const float2* ks = g_ks + n*NC*HH*HH + r;
    const float2* cp = (const float2*)coil + n*NC*HH*HH + r;
    #pragma unroll 5
    for (int c = 0; c < NC; c++){
        float2 w2 = ks[c*HH*HH];
        float2 cc = cp[c*HH*HH];
        ax += w2.x*cc.x + w2.y*cc.y;
        ay += w2.y*cc.x - w2.x*cc.y;
    }
    float sg  = ((x + y) & 1) ? -1.f : 1.f;
    float lam = lamb[0] * sg;
    float2 uv = ((const float2*)u)[idx];
    float2 rv  = g_ru[idx];
    float2 rv2 = g_ru2[idx];
    ((float2*)outp)[idx] = make_float2(uv.x - rv.x - rv2.x - lam*ax,
                                       uv.y - rv.y - rv2.y - lam*ay);
}

// ---------------- launch ---------------------------------------------------
extern "C" void kernel_launch(void* const* d_in, const int* in_sizes, int n_in,
                              void* d_out, int out_size){
    const float* u     = (const float*)d_in[0];   // (4,320,320,2)
    const float* f     = (const float*)d_in[1];   // (4,15,320,320,2)
    const float* coil  = (const float*)d_in[2];   // (4,15,320,320,2)
    const float* mask  = (const float*)d_in[3];   // (4,320,320)
    const float* ck    = (const float*)d_in[4];   // (32,1,11,11,2)
    const float* w_    = (const float*)d_in[5];   // (1,32,1,1,31)
    const float* mu_   = (const float*)d_in[6];   // (31,)
    const float* sig   = (const float*)d_in[7];   // (1,)
    const float* lamb  = (const float*)d_in[8];   // (1,)
    float* outp = (float*)d_out;

    kprep<<<(FEATS*40*8 + 255)/256, 256>>>(ck);
    kpad<<<(NB*UPD*UPD + 255)/256, 256>>>(u);
    kconv_mma<<<dim3(11, 22, NB), 256>>>(ck, w_, mu_, sig);
    kconvT_mma<<<dim3(12, 20, NB*2), 256>>>();
    kfft_row_fwd<<<NB*NC*80, 320>>>(u, coil);
    kfft_col<<<NB*NC*80, 320>>>(f, mask);
    kfft_row_inv_a<<<NB*NC*80, 320>>>();
    kcombine<<<(NB*HH*HH + 255)/256, 256>>>(u, coil, lamb, outp);
}